// round 14
// baseline (speedup 1.0000x reference)
#include <cuda_runtime.h>
#include <cuda_fp16.h>
#include <math.h>
#include <stdint.h>

#define DD 1024
#define BSZ 256

// ---- scratch globals --------------------------------------------------------
__device__ __half g_h16[BSZ * DD];
__device__ float  g_logits[BSZ * DD];
__device__ __half g_text2_h[BSZ * DD];
__device__ __half g_pretxt_h[BSZ * DD];
__device__ __half g_pimgb_h[BSZ * DD];
__device__ __half g_rw2_h[DD * DD];    // rw2 fp16 [k][n]
__device__ __half g_aw1_h[DD * DD];
__device__ __half g_aw2_h[DD * DD];
__device__ __half g_rw1_h[2 * DD * DD];
__device__ __half g_text_h[BSZ * DD];
__device__ __half g_img_h[BSZ * DD];

// ---- cp.async helpers ------------------------------------------------------
#define CP_ASYNC16(dst, src) \
    asm volatile("cp.async.cg.shared.global [%0], [%1], 16;" \
        :: "r"(dst), "l"(src) : "memory")
#define CP_COMMIT() asm volatile("cp.async.commit_group;" ::: "memory")
#define CP_WAIT0()  asm volatile("cp.async.wait_group 0;" ::: "memory")
#define CP_WAIT2()  asm volatile("cp.async.wait_group 2;" ::: "memory")

// ---- mma.sync / ldmatrix ----------------------------------------------------
#define LDSM_X4(r0,r1,r2,r3,addr) \
    asm volatile("ldmatrix.sync.aligned.m8n8.x4.shared.b16 {%0,%1,%2,%3}, [%4];" \
        : "=r"(r0),"=r"(r1),"=r"(r2),"=r"(r3) : "r"(addr))
#define LDSM_X4_T(r0,r1,r2,r3,addr) \
    asm volatile("ldmatrix.sync.aligned.m8n8.x4.trans.shared.b16 {%0,%1,%2,%3}, [%4];" \
        : "=r"(r0),"=r"(r1),"=r"(r2),"=r"(r3) : "r"(addr))
#define MMA_F16F32(d0,d1,d2,d3,a0,a1,a2,a3,b0,b1) \
    asm volatile("mma.sync.aligned.m16n8k16.row.col.f32.f16.f16.f32 " \
        "{%0,%1,%2,%3}, {%4,%5,%6,%7}, {%8,%9}, {%0,%1,%2,%3};" \
        : "+f"(d0),"+f"(d1),"+f"(d2),"+f"(d3) \
        : "r"(a0),"r"(a1),"r"(a2),"r"(a3),"r"(b0),"r"(b1))

// ============================================================================
// Prepass: convert all fp32 operands to fp16 (one launch, fully parallel).
// ============================================================================
__global__ void __launch_bounds__(256)
conv_all(const float* __restrict__ aw1, const float* __restrict__ aw2,
         const float* __restrict__ rw1, const float* __restrict__ rw2,
         const float* __restrict__ text, const float* __restrict__ image,
         __half* __restrict__ aw1h, __half* __restrict__ aw2h,
         __half* __restrict__ rw1h, __half* __restrict__ rw2h,
         __half* __restrict__ texth, __half* __restrict__ imgh)
{
    const int b = blockIdx.x;
    const float* src; __half* dst; int off;
    if      (b < 1024) { src = aw1;   dst = aw1h;  off = b; }
    else if (b < 2048) { src = aw2;   dst = aw2h;  off = b - 1024; }
    else if (b < 4096) { src = rw1;   dst = rw1h;  off = b - 2048; }
    else if (b < 5120) { src = rw2;   dst = rw2h;  off = b - 4096; }
    else if (b < 5376) { src = text;  dst = texth; off = b - 5120; }
    else               { src = image; dst = imgh;  off = b - 5376; }
    const int idx = off * 1024 + threadIdx.x * 4;
    float4 v = *(const float4*)(src + idx);
    __half2 h0 = __floats2half2_rn(v.x, v.y);
    __half2 h1 = __floats2half2_rn(v.z, v.w);
    uint2 o; o.x = *(uint32_t*)&h0; o.y = *(uint32_t*)&h1;
    *(uint2*)(dst + idx) = o;
}

// ============================================================================
// Small-chain GEMMs: all-fp16, 4-stage cp.async pipeline, 32x64 CTA tile.
// (unchanged from round 13)
// ============================================================================
template <bool RELU, bool HAS_BIAS, bool HALFOUT>
__device__ __forceinline__ void hgemm_ms(
    const __half* __restrict__ A, const __half* __restrict__ B,
    const float* __restrict__ bias, void* __restrict__ Cv)
{
    __shared__ __half As[4][32][40];
    __shared__ __half Bs[4][32][72];

    const int t    = threadIdx.x;
    const int lane = t & 31;
    const int warp = t >> 5;
    const int m0 = blockIdx.y * 32;
    const int n0 = blockIdx.x * 64;

    const int wm = (warp >> 1) * 16;
    const int wn = (warp & 1) * 32;

    const int ar = t >> 2;
    const int ac = (t & 3) * 8;
    const int br = t >> 2;
    const int bc = (t & 3) * 16;

    const __half* Arow = A + (size_t)(m0 + ar) * DD + ac;
    const __half* Brow = B + (size_t)br * DD + n0 + bc;

    const uint32_t adst0 = (uint32_t)__cvta_generic_to_shared(&As[0][ar][ac]);
    const uint32_t bdst0 = (uint32_t)__cvta_generic_to_shared(&Bs[0][br][bc]);

    const uint32_t aBase = (uint32_t)__cvta_generic_to_shared(
        &As[0][wm + ((lane >> 3) & 1) * 8 + (lane & 7)][(lane >> 4) * 8]);
    const uint32_t bBase = (uint32_t)__cvta_generic_to_shared(
        &Bs[0][((lane >> 3) & 1) * 8 + (lane & 7)][wn + (lane >> 4) * 8]);

    float acc[4][4] = {};

    #pragma unroll
    for (int q = 0; q < 3; q++) {
        const uint32_t ad = adst0 + q * 2560;
        const uint32_t bd = bdst0 + q * 4608;
        const __half* as = Arow + q * 32;
        const __half* bs = Brow + (size_t)(q * 32) * DD;
        CP_ASYNC16(ad, as);
        CP_ASYNC16(bd,      bs);
        CP_ASYNC16(bd + 16, bs + 8);
        CP_COMMIT();
    }

    for (int c = 0; c < 32; c++) {
        CP_WAIT2();
        __syncthreads();

        if (c < 29) {
            const int q = c + 3;
            const uint32_t ad = adst0 + (q & 3) * 2560;
            const uint32_t bd = bdst0 + (q & 3) * 4608;
            const __half* as = Arow + q * 32;
            const __half* bs = Brow + (size_t)(q * 32) * DD;
            CP_ASYNC16(ad, as);
            CP_ASYNC16(bd,      bs);
            CP_ASYNC16(bd + 16, bs + 8);
        }
        CP_COMMIT();

        const uint32_t aB = aBase + (c & 3) * 2560;
        const uint32_t bB = bBase + (c & 3) * 4608;
        #pragma unroll
        for (int ks = 0; ks < 2; ks++) {
            const int kk = ks * 16;
            unsigned a[4];
            LDSM_X4(a[0], a[1], a[2], a[3], aB + kk * 2);
            unsigned b[4][2];
            #pragma unroll
            for (int bt = 0; bt < 2; bt++)
                LDSM_X4_T(b[bt*2][0], b[bt*2][1], b[bt*2+1][0], b[bt*2+1][1],
                          bB + kk * 144 + bt * 32);
            #pragma unroll
            for (int nt = 0; nt < 4; nt++)
                MMA_F16F32(acc[nt][0], acc[nt][1], acc[nt][2], acc[nt][3],
                           a[0], a[1], a[2], a[3], b[nt][0], b[nt][1]);
        }
    }

    const int rbase = wm + (lane >> 2);
    #pragma unroll
    for (int half = 0; half < 2; half++) {
        const int r = m0 + rbase + half * 8;
        #pragma unroll
        for (int nt = 0; nt < 4; nt++) {
            const int col = n0 + wn + nt * 8 + (lane & 3) * 2;
            float v0 = acc[nt][half * 2 + 0];
            float v1 = acc[nt][half * 2 + 1];
            if (HAS_BIAS) { v0 += bias[col]; v1 += bias[col + 1]; }
            if (RELU) { v0 = fmaxf(v0, 0.0f); v1 = fmaxf(v1, 0.0f); }
            if (HALFOUT) {
                __half2 h = __floats2half2_rn(v0, v1);
                *(uint32_t*)((__half*)Cv + (size_t)r * DD + col) = *(uint32_t*)&h;
            } else {
                float2 f = make_float2(v0, v1);
                *(float2*)((float*)Cv + (size_t)r * DD + col) = f;
            }
        }
    }
}

__global__ void __launch_bounds__(128)
small_pair(const __half* __restrict__ text16, const __half* __restrict__ aw1h,
           const float* __restrict__ ab1, __half* __restrict__ h16,
           const __half* __restrict__ img16, const __half* __restrict__ rw1h,
           const float* __restrict__ rb1, __half* __restrict__ pimgb)
{
    if (blockIdx.z == 0)
        hgemm_ms<true, true, true>(text16, aw1h, ab1, h16);
    else
        hgemm_ms<false, true, true>(img16, rw1h, rb1, pimgb);
}

__global__ void __launch_bounds__(128)
small_logits(const __half* __restrict__ h16, const __half* __restrict__ aw2h,
             const float* __restrict__ ab2, float* __restrict__ logits)
{
    hgemm_ms<false, true, false>(h16, aw2h, ab2, logits);
}

__global__ void __launch_bounds__(128)
small_pretxt(const __half* __restrict__ text2, const __half* __restrict__ rw1bh,
             __half* __restrict__ pretxt)
{
    hgemm_ms<false, false, true>(text2, rw1bh, nullptr, pretxt);
}

// ---------------------------------------------------------------------------
__global__ void __launch_bounds__(256)
softmax_mul(const float* __restrict__ logits, const float* __restrict__ text,
            __half* __restrict__ out)
{
    const int row = blockIdx.x;
    const int t   = threadIdx.x;
    const float* l = logits + (size_t)row * DD;
    __shared__ float smax[8];
    __shared__ float ssum[8];

    float m = -1e30f;
    #pragma unroll
    for (int k = t; k < DD; k += 256) m = fmaxf(m, l[k]);
    #pragma unroll
    for (int o = 16; o > 0; o >>= 1)
        m = fmaxf(m, __shfl_xor_sync(0xffffffffu, m, o));
    if ((t & 31) == 0) smax[t >> 5] = m;
    __syncthreads();
    float rowmax = smax[0];
    #pragma unroll
    for (int w = 1; w < 8; w++) rowmax = fmaxf(rowmax, smax[w]);

    float s = 0.0f;
    #pragma unroll
    for (int k = t; k < DD; k += 256) s += expf(l[k] - rowmax);
    #pragma unroll
    for (int o = 16; o > 0; o >>= 1)
        s += __shfl_xor_sync(0xffffffffu, s, o);
    if ((t & 31) == 0) ssum[t >> 5] = s;
    __syncthreads();
    float tot = 0.0f;
    #pragma unroll
    for (int w = 0; w < 8; w++) tot += ssum[w];
    const float inv = 1.0f / tot;

    const float* tr = text + (size_t)row * DD;
    __half* orow = out + (size_t)row * DD;
    #pragma unroll
    for (int k = t * 2; k < DD; k += 512) {
        float w0 = tr[k]     * (expf(l[k]     - rowmax) * inv);
        float w1 = tr[k + 1] * (expf(l[k + 1] - rowmax) * inv);
        __half2 h = __floats2half2_rn(w0, w1);
        *(uint32_t*)(orow + k) = *(uint32_t*)&h;
    }
}

// ============================================================================
// Big GEMM — HETEROGENEOUS: m-tiles with y%9==0 run a SIMT fp32 FFMA path
// (FMA pipe, otherwise idle); the rest run the proven HMMA path (tensor pipe).
// Both personalities in ONE kernel so the block scheduler freely mixes
// ~1 HMMA + 1 FFMA CTA per SM; throughputs add (~287 + ~40 TF/s).
// Shared memory overlaid in one 37888B buffer.
// ============================================================================
__device__ __forceinline__ uint4 fuse_relu_f16(uint4 p, uint4 t)
{
    const __half2 z = __float2half2_rn(0.0f);
    uint4 r;
    const __half2* pp = (const __half2*)&p;
    const __half2* tt = (const __half2*)&t;
    __half2* rr = (__half2*)&r;
    #pragma unroll
    for (int q = 0; q < 4; q++)
        rr[q] = __hmax2(__hadd2(pp[q], tt[q]), z);
    return r;
}

__global__ void __launch_bounds__(256, 2)
big_gemm_hybrid(const __half* __restrict__ pretxt,
                const __half* __restrict__ pimgb,
                const __half* __restrict__ rw2h,
                const float* __restrict__ rw2f,
                const float* __restrict__ image,
                const float* __restrict__ rb2,
                float* __restrict__ out)
{
    __shared__ __align__(16) char smemraw[37888];

    const int t    = threadIdx.x;
    const int lane = t & 31;
    const int warp = t >> 5;
    const int n0 = blockIdx.x * 128;
    const int m0 = blockIdx.y * 128;
    const int i  = m0 >> 8;
    const int j0 = m0 & 255;

    const __half* ptrow = pretxt + (size_t)i * DD;

    if (blockIdx.y % 9 != 0) {
        // ==================== HMMA path (round-13, flat-indexed) ====================
        __half* As0 = (__half*)smemraw;              // [2][128][40]
        __half* Bs0 = (__half*)(smemraw + 20480);    // [2][32][136]
        const uint32_t ASTG = 10240, BSTG = 8704;

        const int wm = (warp >> 2) * 64;
        const int wn = (warp & 3) * 32;

        const int ar  = t >> 1;
        const int akv = (t & 1) * 16;
        const int br  = t >> 3;
        const int bnv = (t & 7) * 16;

        const __half* parow = pimgb + (size_t)(j0 + ar) * DD + akv;
        const __half* pbrow = rw2h + (size_t)br * DD + n0 + bnv;

        const uint32_t bdst0 = (uint32_t)__cvta_generic_to_shared(
            Bs0 + br * 136 + bnv);
        const uint32_t aBase = (uint32_t)__cvta_generic_to_shared(
            As0 + (wm + ((lane >> 3) & 1) * 8 + (lane & 7)) * 40 + (lane >> 4) * 8);
        const uint32_t bBase = (uint32_t)__cvta_generic_to_shared(
            Bs0 + (((lane >> 3) & 1) * 8 + (lane & 7)) * 136 + wn + (lane >> 4) * 8);

        float acc[4][4][4] = {};

        CP_ASYNC16(bdst0,      pbrow);
        CP_ASYNC16(bdst0 + 16, pbrow + 8);
        CP_COMMIT();
        {
            uint4 pv0 = *(const uint4*)(parow);
            uint4 pv1 = *(const uint4*)(parow + 8);
            uint4 tv0 = *(const uint4*)(ptrow + akv);
            uint4 tv1 = *(const uint4*)(ptrow + akv + 8);
            *(uint4*)(As0 + ar * 40 + akv)     = fuse_relu_f16(pv0, tv0);
            *(uint4*)(As0 + ar * 40 + akv + 8) = fuse_relu_f16(pv1, tv1);
        }
        CP_WAIT0();
        __syncthreads();

        uint4 pv0, pv1, tv0, tv1;
        for (int c = 0; c < 32; c++) {
            const int s  = c & 1;
            const int ns = s ^ 1;
            const int kn = (c + 1) * 32;

            if (c < 31) {
                CP_ASYNC16(bdst0 + ns * BSTG,      pbrow + (size_t)kn * DD);
                CP_ASYNC16(bdst0 + ns * BSTG + 16, pbrow + (size_t)kn * DD + 8);
                CP_COMMIT();
                pv0 = *(const uint4*)(parow + kn);
                pv1 = *(const uint4*)(parow + kn + 8);
                tv0 = *(const uint4*)(ptrow + kn + akv);
                tv1 = *(const uint4*)(ptrow + kn + akv + 8);
            }

            const uint32_t aB = aBase + s * ASTG;
            const uint32_t bB = bBase + s * BSTG;
            #pragma unroll
            for (int ks = 0; ks < 2; ks++) {
                const int kk = ks * 16;
                unsigned a[4][4];
                #pragma unroll
                for (int mt = 0; mt < 4; mt++)
                    LDSM_X4(a[mt][0], a[mt][1], a[mt][2], a[mt][3],
                            aB + mt * 16 * 80 + kk * 2);
                unsigned b[4][2];
                #pragma unroll
                for (int bt = 0; bt < 2; bt++)
                    LDSM_X4_T(b[bt*2][0], b[bt*2][1], b[bt*2+1][0], b[bt*2+1][1],
                              bB + kk * 272 + bt * 32);
                #pragma unroll
                for (int mt = 0; mt < 4; mt++)
                    #pragma unroll
                    for (int nt = 0; nt < 4; nt++)
                        MMA_F16F32(acc[mt][nt][0], acc[mt][nt][1],
                                   acc[mt][nt][2], acc[mt][nt][3],
                                   a[mt][0], a[mt][1], a[mt][2], a[mt][3],
                                   b[nt][0], b[nt][1]);
            }

            if (c < 31) {
                *(uint4*)(As0 + ns * 5120 + ar * 40 + akv)     = fuse_relu_f16(pv0, tv0);
                *(uint4*)(As0 + ns * 5120 + ar * 40 + akv + 8) = fuse_relu_f16(pv1, tv1);
                CP_WAIT0();
            }
            __syncthreads();
        }

        #pragma unroll
        for (int mt = 0; mt < 4; mt++) {
            const int rbase = wm + mt * 16 + (lane >> 2);
            #pragma unroll
            for (int half = 0; half < 2; half++) {
                const int r = rbase + half * 8;
                const float* img = image + (size_t)(j0 + r) * DD;
                const size_t orow = (size_t)(m0 + r) * DD;
                #pragma unroll
                for (int nt = 0; nt < 4; nt++) {
                    const int col = n0 + wn + nt * 8 + (lane & 3) * 2;
                    float2 im = *(const float2*)(img + col);
                    float2 rb = *(const float2*)(rb2 + col);
                    float2 o;
                    o.x = acc[mt][nt][half * 2 + 0] + im.x + rb.x;
                    o.y = acc[mt][nt][half * 2 + 1] + im.y + rb.y;
                    *(float2*)(out + orow + col) = o;
                }
            }
        }
    } else {
        // ==================== FFMA path (round-1 SIMT, fp32) ====================
        float (*Af)[132] = (float(*)[132])smemraw;           // 8 x 132
        float (*Bf)[132] = (float(*)[132])(smemraw + 4224);  // 8 x 132

        const int tx = t & 15, ty = t >> 4;
        const int ar  = t >> 1;          // 0..127
        const int akv = (t & 1) * 4;     // 0 or 4
        const int bk  = t >> 5;          // 0..7
        const int bnv = (t & 31) * 4;    // 0..124

        const __half* parow = pimgb + (size_t)(j0 + ar) * DD + akv;
        const float*  brow  = rw2f + (size_t)bk * DD + n0 + bnv;

        float acc[8][8] = {};

        for (int k0 = 0; k0 < DD; k0 += 8) {
            uint2 pu = *(const uint2*)(parow + k0);
            uint2 tu = *(const uint2*)(ptrow + k0 + akv);
            float4 b4 = *(const float4*)(brow + (size_t)k0 * DD);
            __syncthreads();
            float2 p0 = __half22float2(*(__half2*)&pu.x);
            float2 p1 = __half22float2(*(__half2*)&pu.y);
            float2 q0 = __half22float2(*(__half2*)&tu.x);
            float2 q1 = __half22float2(*(__half2*)&tu.y);
            Af[akv + 0][ar] = fmaxf(p0.x + q0.x, 0.0f);
            Af[akv + 1][ar] = fmaxf(p0.y + q0.y, 0.0f);
            Af[akv + 2][ar] = fmaxf(p1.x + q1.x, 0.0f);
            Af[akv + 3][ar] = fmaxf(p1.y + q1.y, 0.0f);
            *(float4*)(&Bf[bk][bnv]) = b4;
            __syncthreads();

            #pragma unroll
            for (int kk = 0; kk < 8; kk++) {
                float a[8], b[8];
                *(float4*)(a)     = *(const float4*)(&Af[kk][ty * 4]);
                *(float4*)(a + 4) = *(const float4*)(&Af[kk][64 + ty * 4]);
                *(float4*)(b)     = *(const float4*)(&Bf[kk][tx * 4]);
                *(float4*)(b + 4) = *(const float4*)(&Bf[kk][64 + tx * 4]);
                #pragma unroll
                for (int r = 0; r < 8; r++)
                    #pragma unroll
                    for (int c = 0; c < 8; c++)
                        acc[r][c] = fmaf(a[r], b[c], acc[r][c]);
            }
        }

        #pragma unroll
        for (int r = 0; r < 8; r++) {
            const int lr = (r < 4) ? (ty * 4 + r) : (64 + ty * 4 + (r - 4));
            const size_t orow = (size_t)(m0 + lr) * DD;
            const float* img = image + (size_t)(j0 + lr) * DD;
            #pragma unroll
            for (int cp = 0; cp < 2; cp++) {
                const int lc = cp * 64 + tx * 4;
                const int cb = cp * 4;
                float4 im = *(const float4*)(img + n0 + lc);
                float4 rb = *(const float4*)(rb2 + n0 + lc);
                float4 o;
                o.x = acc[r][cb + 0] + im.x + rb.x;
                o.y = acc[r][cb + 1] + im.y + rb.y;
                o.z = acc[r][cb + 2] + im.z + rb.z;
                o.w = acc[r][cb + 3] + im.w + rb.w;
                *(float4*)(out + orow + n0 + lc) = o;
            }
        }
    }
}

// ---------------------------------------------------------------------------
extern "C" void kernel_launch(void* const* d_in, const int* in_sizes, int n_in,
                              void* d_out, int out_size)
{
    const float* image = (const float*)d_in[0];
    const float* text  = (const float*)d_in[1];
    const float* aw1   = (const float*)d_in[2];
    const float* ab1   = (const float*)d_in[3];
    const float* aw2   = (const float*)d_in[4];
    const float* ab2   = (const float*)d_in[5];
    const float* rw1   = (const float*)d_in[6];
    const float* rb1   = (const float*)d_in[7];
    const float* rw2   = (const float*)d_in[8];
    const float* rb2   = (const float*)d_in[9];
    float* out = (float*)d_out;

    __half *h16_p, *text2_p, *pretxt_p, *pimgb_p, *rw2h_p;
    __half *aw1h_p, *aw2h_p, *rw1h_p, *texth_p, *imgh_p;
    float *logits_p;
    cudaGetSymbolAddress((void**)&h16_p,    g_h16);
    cudaGetSymbolAddress((void**)&logits_p, g_logits);
    cudaGetSymbolAddress((void**)&text2_p,  g_text2_h);
    cudaGetSymbolAddress((void**)&pretxt_p, g_pretxt_h);
    cudaGetSymbolAddress((void**)&pimgb_p,  g_pimgb_h);
    cudaGetSymbolAddress((void**)&rw2h_p,   g_rw2_h);
    cudaGetSymbolAddress((void**)&aw1h_p,   g_aw1_h);
    cudaGetSymbolAddress((void**)&aw2h_p,   g_aw2_h);
    cudaGetSymbolAddress((void**)&rw1h_p,   g_rw1_h);
    cudaGetSymbolAddress((void**)&texth_p,  g_text_h);
    cudaGetSymbolAddress((void**)&imgh_p,   g_img_h);

    dim3 blk128(128);
    dim3 gsmall(16, 8);

    conv_all<<<5632, 256>>>(aw1, aw2, rw1, rw2, text, image,
                            aw1h_p, aw2h_p, rw1h_p, rw2h_p, texth_p, imgh_p);
    small_pair<<<dim3(16, 8, 2), blk128>>>(
        texth_p, aw1h_p, ab1, h16_p, imgh_p, rw1h_p, rb1, pimgb_p);
    small_logits<<<gsmall, blk128>>>(h16_p, aw2h_p, ab2, logits_p);
    softmax_mul<<<BSZ, 256>>>(logits_p, text, text2_p);
    small_pretxt<<<gsmall, blk128>>>(text2_p, rw1h_p + (size_t)DD * DD, pretxt_p);
    // hybrid big GEMM: tensor + FMA pipes concurrently
    big_gemm_hybrid<<<dim3(8, 512), 256>>>(
        pretxt_p, pimgb_p, rw2h_p, rw2, image, rb2, out);
}

// round 15
// speedup vs baseline: 1.6981x; 1.6981x over previous
#include <cuda_runtime.h>
#include <cuda_fp16.h>
#include <math.h>
#include <stdint.h>

#define DD 1024
#define BSZ 256

// ---- scratch globals --------------------------------------------------------
__device__ __half g_h16[BSZ * DD];
__device__ float  g_logits[BSZ * DD];
__device__ __half g_text2_h[BSZ * DD];
__device__ __half g_pretxt_h[BSZ * DD];
__device__ __half g_pimgb_h[BSZ * DD];
__device__ __half g_rw2_h[DD * DD];    // rw2 fp16 [k][n]
__device__ __half g_aw1_h[DD * DD];
__device__ __half g_aw2_h[DD * DD];
__device__ __half g_rw1_h[2 * DD * DD];
__device__ __half g_text_h[BSZ * DD];
__device__ __half g_img_h[BSZ * DD];

// ---- cp.async helpers ------------------------------------------------------
#define CP_ASYNC16(dst, src) \
    asm volatile("cp.async.cg.shared.global [%0], [%1], 16;" \
        :: "r"(dst), "l"(src) : "memory")
#define CP_COMMIT() asm volatile("cp.async.commit_group;" ::: "memory")
#define CP_WAIT0()  asm volatile("cp.async.wait_group 0;" ::: "memory")
#define CP_WAIT2()  asm volatile("cp.async.wait_group 2;" ::: "memory")

// ---- mma.sync / ldmatrix ----------------------------------------------------
#define LDSM_X4(r0,r1,r2,r3,addr) \
    asm volatile("ldmatrix.sync.aligned.m8n8.x4.shared.b16 {%0,%1,%2,%3}, [%4];" \
        : "=r"(r0),"=r"(r1),"=r"(r2),"=r"(r3) : "r"(addr))
#define LDSM_X4_T(r0,r1,r2,r3,addr) \
    asm volatile("ldmatrix.sync.aligned.m8n8.x4.trans.shared.b16 {%0,%1,%2,%3}, [%4];" \
        : "=r"(r0),"=r"(r1),"=r"(r2),"=r"(r3) : "r"(addr))
#define MMA_F16F32(d0,d1,d2,d3,a0,a1,a2,a3,b0,b1) \
    asm volatile("mma.sync.aligned.m16n8k16.row.col.f32.f16.f16.f32 " \
        "{%0,%1,%2,%3}, {%4,%5,%6,%7}, {%8,%9}, {%0,%1,%2,%3};" \
        : "+f"(d0),"+f"(d1),"+f"(d2),"+f"(d3) \
        : "r"(a0),"r"(a1),"r"(a2),"r"(a3),"r"(b0),"r"(b1))

// ============================================================================
// Prepass: convert all fp32 operands to fp16 (one launch, fully parallel).
// Segments: [0,1024) aw1 | [1024,2048) aw2 | [2048,4096) rw1 |
// [4096,5120) rw2 | [5120,5376) text | [5376,5632) image. 1024 elems/block.
// ============================================================================
__global__ void __launch_bounds__(256)
conv_all(const float* __restrict__ aw1, const float* __restrict__ aw2,
         const float* __restrict__ rw1, const float* __restrict__ rw2,
         const float* __restrict__ text, const float* __restrict__ image,
         __half* __restrict__ aw1h, __half* __restrict__ aw2h,
         __half* __restrict__ rw1h, __half* __restrict__ rw2h,
         __half* __restrict__ texth, __half* __restrict__ imgh)
{
    const int b = blockIdx.x;
    const float* src; __half* dst; int off;
    if      (b < 1024) { src = aw1;   dst = aw1h;  off = b; }
    else if (b < 2048) { src = aw2;   dst = aw2h;  off = b - 1024; }
    else if (b < 4096) { src = rw1;   dst = rw1h;  off = b - 2048; }
    else if (b < 5120) { src = rw2;   dst = rw2h;  off = b - 4096; }
    else if (b < 5376) { src = text;  dst = texth; off = b - 5120; }
    else               { src = image; dst = imgh;  off = b - 5376; }
    const int idx = off * 1024 + threadIdx.x * 4;
    float4 v = *(const float4*)(src + idx);
    __half2 h0 = __floats2half2_rn(v.x, v.y);
    __half2 h1 = __floats2half2_rn(v.z, v.w);
    uint2 o; o.x = *(uint32_t*)&h0; o.y = *(uint32_t*)&h1;
    *(uint2*)(dst + idx) = o;
}

// ============================================================================
// Small-chain GEMMs: all-fp16, 4-stage cp.async pipeline, 32x64 CTA tile.
// C[256 x 1024] = A[256 x 1024] @ B[1024 x 1024] (+bias)(relu)
// Grid (16,8) = 128 CTAs; 128 threads = 4 warps (2m x 2n), warp tile 16x32.
// One __syncthreads per 32-K chunk; loads run 3 chunks ahead.
// ============================================================================
template <bool RELU, bool HAS_BIAS, bool HALFOUT>
__device__ __forceinline__ void hgemm_ms(
    const __half* __restrict__ A, const __half* __restrict__ B,
    const float* __restrict__ bias, void* __restrict__ Cv)
{
    __shared__ __half As[4][32][40];   // [m][k], row 80B; 2560B/stage
    __shared__ __half Bs[4][32][72];   // [k][n], row 144B; 4608B/stage

    const int t    = threadIdx.x;
    const int lane = t & 31;
    const int warp = t >> 5;             // 0..3
    const int m0 = blockIdx.y * 32;
    const int n0 = blockIdx.x * 64;

    const int wm = (warp >> 1) * 16;     // 0 or 16
    const int wn = (warp & 1) * 32;      // 0 or 32

    // loaders: A 32r x 32k (4 thr/row, 16B each); B 32k x 64n (4 thr/row, 32B)
    const int ar = t >> 2;               // 0..31
    const int ac = (t & 3) * 8;          // 0,8,16,24 (elems)
    const int br = t >> 2;               // 0..31
    const int bc = (t & 3) * 16;         // 0..48 (elems)

    const __half* Arow = A + (size_t)(m0 + ar) * DD + ac;
    const __half* Brow = B + (size_t)br * DD + n0 + bc;

    const uint32_t adst0 = (uint32_t)__cvta_generic_to_shared(&As[0][ar][ac]);
    const uint32_t bdst0 = (uint32_t)__cvta_generic_to_shared(&Bs[0][br][bc]);

    const uint32_t aBase = (uint32_t)__cvta_generic_to_shared(
        &As[0][wm + ((lane >> 3) & 1) * 8 + (lane & 7)][(lane >> 4) * 8]);
    const uint32_t bBase = (uint32_t)__cvta_generic_to_shared(
        &Bs[0][((lane >> 3) & 1) * 8 + (lane & 7)][wn + (lane >> 4) * 8]);

    float acc[4][4] = {};   // [nt][reg] (single m-tile of 16)

    // ---- prologue: issue chunks 0..2 into slots 0..2 ----
    #pragma unroll
    for (int q = 0; q < 3; q++) {
        const uint32_t ad = adst0 + q * 2560;
        const uint32_t bd = bdst0 + q * 4608;
        const __half* as = Arow + q * 32;
        const __half* bs = Brow + (size_t)(q * 32) * DD;
        CP_ASYNC16(ad, as);
        CP_ASYNC16(bd,      bs);
        CP_ASYNC16(bd + 16, bs + 8);
        CP_COMMIT();
    }

    for (int c = 0; c < 32; c++) {       // FULL K: 32 chunks of 32
        CP_WAIT2();          // chunk c complete (≤2 newer groups outstanding)
        __syncthreads();     // all warps done with slot (c-1)&3; data visible

        if (c < 29) {        // issue chunk c+3 into slot (c+3)&3
            const int q = c + 3;
            const uint32_t ad = adst0 + (q & 3) * 2560;
            const uint32_t bd = bdst0 + (q & 3) * 4608;
            const __half* as = Arow + q * 32;
            const __half* bs = Brow + (size_t)(q * 32) * DD;
            CP_ASYNC16(ad, as);
            CP_ASYNC16(bd,      bs);
            CP_ASYNC16(bd + 16, bs + 8);
        }
        CP_COMMIT();         // always commit (keeps group numbering)

        // ---- compute slot c&3 ----
        const uint32_t aB = aBase + (c & 3) * 2560;
        const uint32_t bB = bBase + (c & 3) * 4608;
        #pragma unroll
        for (int ks = 0; ks < 2; ks++) {
            const int kk = ks * 16;
            unsigned a[4];
            LDSM_X4(a[0], a[1], a[2], a[3], aB + kk * 2);
            unsigned b[4][2];
            #pragma unroll
            for (int bt = 0; bt < 2; bt++)
                LDSM_X4_T(b[bt*2][0], b[bt*2][1], b[bt*2+1][0], b[bt*2+1][1],
                          bB + kk * 144 + bt * 32);
            #pragma unroll
            for (int nt = 0; nt < 4; nt++)
                MMA_F16F32(acc[nt][0], acc[nt][1], acc[nt][2], acc[nt][3],
                           a[0], a[1], a[2], a[3], b[nt][0], b[nt][1]);
        }
    }

    // ---- epilogue ----
    const int rbase = wm + (lane >> 2);
    #pragma unroll
    for (int half = 0; half < 2; half++) {
        const int r = m0 + rbase + half * 8;
        #pragma unroll
        for (int nt = 0; nt < 4; nt++) {
            const int col = n0 + wn + nt * 8 + (lane & 3) * 2;
            float v0 = acc[nt][half * 2 + 0];
            float v1 = acc[nt][half * 2 + 1];
            if (HAS_BIAS) { v0 += bias[col]; v1 += bias[col + 1]; }
            if (RELU) { v0 = fmaxf(v0, 0.0f); v1 = fmaxf(v1, 0.0f); }
            if (HALFOUT) {
                __half2 h = __floats2half2_rn(v0, v1);
                *(uint32_t*)((__half*)Cv + (size_t)r * DD + col) = *(uint32_t*)&h;
            } else {
                float2 f = make_float2(v0, v1);
                *(float2*)((float*)Cv + (size_t)r * DD + col) = f;
            }
        }
    }
}

// z=0: h16 = fp16(relu(text16@aw1+ab1));  z=1: pimgb = fp16(img16@rw1a+rb1)
__global__ void __launch_bounds__(128)
small_pair(const __half* __restrict__ text16, const __half* __restrict__ aw1h,
           const float* __restrict__ ab1, __half* __restrict__ h16,
           const __half* __restrict__ img16, const __half* __restrict__ rw1h,
           const float* __restrict__ rb1, __half* __restrict__ pimgb)
{
    if (blockIdx.z == 0)
        hgemm_ms<true, true, true>(text16, aw1h, ab1, h16);
    else
        hgemm_ms<false, true, true>(img16, rw1h, rb1, pimgb);
}

__global__ void __launch_bounds__(128)
small_logits(const __half* __restrict__ h16, const __half* __restrict__ aw2h,
             const float* __restrict__ ab2, float* __restrict__ logits)
{
    hgemm_ms<false, true, false>(h16, aw2h, ab2, logits);
}

__global__ void __launch_bounds__(128)
small_pretxt(const __half* __restrict__ text2, const __half* __restrict__ rw1bh,
             __half* __restrict__ pretxt)
{
    hgemm_ms<false, false, true>(text2, rw1bh, nullptr, pretxt);
}

// ---------------------------------------------------------------------------
// text2 = fp16(text * softmax(logits, axis=1))
__global__ void __launch_bounds__(256)
softmax_mul(const float* __restrict__ logits, const float* __restrict__ text,
            __half* __restrict__ out)
{
    const int row = blockIdx.x;
    const int t   = threadIdx.x;
    const float* l = logits + (size_t)row * DD;
    __shared__ float smax[8];
    __shared__ float ssum[8];

    float m = -1e30f;
    #pragma unroll
    for (int k = t; k < DD; k += 256) m = fmaxf(m, l[k]);
    #pragma unroll
    for (int o = 16; o > 0; o >>= 1)
        m = fmaxf(m, __shfl_xor_sync(0xffffffffu, m, o));
    if ((t & 31) == 0) smax[t >> 5] = m;
    __syncthreads();
    float rowmax = smax[0];
    #pragma unroll
    for (int w = 1; w < 8; w++) rowmax = fmaxf(rowmax, smax[w]);

    float s = 0.0f;
    #pragma unroll
    for (int k = t; k < DD; k += 256) s += expf(l[k] - rowmax);
    #pragma unroll
    for (int o = 16; o > 0; o >>= 1)
        s += __shfl_xor_sync(0xffffffffu, s, o);
    if ((t & 31) == 0) ssum[t >> 5] = s;
    __syncthreads();
    float tot = 0.0f;
    #pragma unroll
    for (int w = 0; w < 8; w++) tot += ssum[w];
    const float inv = 1.0f / tot;

    const float* tr = text + (size_t)row * DD;
    __half* orow = out + (size_t)row * DD;
    #pragma unroll
    for (int k = t * 2; k < DD; k += 512) {
        float w0 = tr[k]     * (expf(l[k]     - rowmax) * inv);
        float w1 = tr[k + 1] * (expf(l[k + 1] - rowmax) * inv);
        __half2 h = __floats2half2_rn(w0, w1);
        *(uint32_t*)(orow + k) = *(uint32_t*)&h;
    }
}

// ============================================================================
// Big GEMM on mma.sync (fp16 in, fp32 accum) — at the sm_103 register-MMA
// issue floor: CTA 128x128, BK=32, 8 warps (2m x 4n), warp tile 64x32,
// 2 CTAs/SM, double-buffered, cp.async for B, SMEM-side relu(pretxt+pimgb)
// A synthesis.
// ============================================================================
__device__ __forceinline__ uint4 fuse_relu_f16(uint4 p, uint4 t)
{
    const __half2 z = __float2half2_rn(0.0f);
    uint4 r;
    const __half2* pp = (const __half2*)&p;
    const __half2* tt = (const __half2*)&t;
    __half2* rr = (__half2*)&r;
    #pragma unroll
    for (int q = 0; q < 4; q++)
        rr[q] = __hmax2(__hadd2(pp[q], tt[q]), z);
    return r;
}

__global__ void __launch_bounds__(256, 2)
big_gemm_mma(const __half* __restrict__ pretxt,
             const __half* __restrict__ pimgb,
             const __half* __restrict__ rw2,
             const float* __restrict__ image,
             const float* __restrict__ rb2,
             float* __restrict__ out)
{
    __shared__ __half As[2][128][40];   // [m][k], 80B rows
    __shared__ __half Bs[2][32][136];   // [k][n], 272B rows

    const uint32_t ASTG = 128 * 40 * 2;
    const uint32_t BSTG = 32 * 136 * 2;

    const int t    = threadIdx.x;
    const int lane = t & 31;
    const int warp = t >> 5;
    const int n0 = blockIdx.x * 128;
    const int m0 = blockIdx.y * 128;
    const int i  = m0 >> 8;
    const int j0 = m0 & 255;

    const int wm = (warp >> 2) * 64;
    const int wn = (warp & 3) * 32;

    const int ar  = t >> 1;
    const int akv = (t & 1) * 16;
    const int br  = t >> 3;
    const int bnv = (t & 7) * 16;

    const __half* ptrow = pretxt + (size_t)i * DD;
    const __half* parow = pimgb + (size_t)(j0 + ar) * DD + akv;
    const __half* pbrow = rw2 + (size_t)br * DD + n0 + bnv;

    const uint32_t bdst0 = (uint32_t)__cvta_generic_to_shared(&Bs[0][br][bnv]);

    const uint32_t aBase = (uint32_t)__cvta_generic_to_shared(
        &As[0][wm + ((lane >> 3) & 1) * 8 + (lane & 7)][(lane >> 4) * 8]);
    const uint32_t bBase = (uint32_t)__cvta_generic_to_shared(
        &Bs[0][((lane >> 3) & 1) * 8 + (lane & 7)][wn + (lane >> 4) * 8]);

    float acc[4][4][4] = {};

    // --- prologue: chunk 0 into stage 0 ---
    CP_ASYNC16(bdst0,      pbrow);
    CP_ASYNC16(bdst0 + 16, pbrow + 8);
    CP_COMMIT();
    {
        uint4 pv0 = *(const uint4*)(parow);
        uint4 pv1 = *(const uint4*)(parow + 8);
        uint4 tv0 = *(const uint4*)(ptrow + akv);
        uint4 tv1 = *(const uint4*)(ptrow + akv + 8);
        *(uint4*)(&As[0][ar][akv])     = fuse_relu_f16(pv0, tv0);
        *(uint4*)(&As[0][ar][akv + 8]) = fuse_relu_f16(pv1, tv1);
    }
    CP_WAIT0();
    __syncthreads();

    uint4 pv0, pv1, tv0, tv1;
    for (int c = 0; c < 32; c++) {
        const int s  = c & 1;
        const int ns = s ^ 1;
        const int kn = (c + 1) * 32;

        if (c < 31) {
            CP_ASYNC16(bdst0 + ns * BSTG,      pbrow + (size_t)kn * DD);
            CP_ASYNC16(bdst0 + ns * BSTG + 16, pbrow + (size_t)kn * DD + 8);
            CP_COMMIT();
            pv0 = *(const uint4*)(parow + kn);
            pv1 = *(const uint4*)(parow + kn + 8);
            tv0 = *(const uint4*)(ptrow + kn + akv);
            tv1 = *(const uint4*)(ptrow + kn + akv + 8);
        }

        const uint32_t aB = aBase + s * ASTG;
        const uint32_t bB = bBase + s * BSTG;
        #pragma unroll
        for (int ks = 0; ks < 2; ks++) {
            const int kk = ks * 16;
            unsigned a[4][4];
            #pragma unroll
            for (int mt = 0; mt < 4; mt++)
                LDSM_X4(a[mt][0], a[mt][1], a[mt][2], a[mt][3],
                        aB + mt * 16 * 80 + kk * 2);
            unsigned b[4][2];
            #pragma unroll
            for (int bt = 0; bt < 2; bt++)
                LDSM_X4_T(b[bt*2][0], b[bt*2][1], b[bt*2+1][0], b[bt*2+1][1],
                          bB + kk * 272 + bt * 32);
            #pragma unroll
            for (int mt = 0; mt < 4; mt++)
                #pragma unroll
                for (int nt = 0; nt < 4; nt++)
                    MMA_F16F32(acc[mt][nt][0], acc[mt][nt][1],
                               acc[mt][nt][2], acc[mt][nt][3],
                               a[mt][0], a[mt][1], a[mt][2], a[mt][3],
                               b[nt][0], b[nt][1]);
        }

        if (c < 31) {
            *(uint4*)(&As[ns][ar][akv])     = fuse_relu_f16(pv0, tv0);
            *(uint4*)(&As[ns][ar][akv + 8]) = fuse_relu_f16(pv1, tv1);
            CP_WAIT0();
        }
        __syncthreads();
    }

    // ---- epilogue: + image[j] + rb2 ----
    #pragma unroll
    for (int mt = 0; mt < 4; mt++) {
        const int rbase = wm + mt * 16 + (lane >> 2);
        #pragma unroll
        for (int half = 0; half < 2; half++) {
            const int r = rbase + half * 8;
            const float* img = image + (size_t)(j0 + r) * DD;
            const size_t orow = (size_t)(m0 + r) * DD;
            #pragma unroll
            for (int nt = 0; nt < 4; nt++) {
                const int col = n0 + wn + nt * 8 + (lane & 3) * 2;
                float2 im = *(const float2*)(img + col);
                float2 rb = *(const float2*)(rb2 + col);
                float2 o;
                o.x = acc[mt][nt][half * 2 + 0] + im.x + rb.x;
                o.y = acc[mt][nt][half * 2 + 1] + im.y + rb.y;
                *(float2*)(out + orow + col) = o;
            }
        }
    }
}

// ---------------------------------------------------------------------------
extern "C" void kernel_launch(void* const* d_in, const int* in_sizes, int n_in,
                              void* d_out, int out_size)
{
    const float* image = (const float*)d_in[0];
    const float* text  = (const float*)d_in[1];
    const float* aw1   = (const float*)d_in[2];
    const float* ab1   = (const float*)d_in[3];
    const float* aw2   = (const float*)d_in[4];
    const float* ab2   = (const float*)d_in[5];
    const float* rw1   = (const float*)d_in[6];
    const float* rb1   = (const float*)d_in[7];
    const float* rw2   = (const float*)d_in[8];
    const float* rb2   = (const float*)d_in[9];
    float* out = (float*)d_out;

    __half *h16_p, *text2_p, *pretxt_p, *pimgb_p, *rw2h_p;
    __half *aw1h_p, *aw2h_p, *rw1h_p, *texth_p, *imgh_p;
    float *logits_p;
    cudaGetSymbolAddress((void**)&h16_p,    g_h16);
    cudaGetSymbolAddress((void**)&logits_p, g_logits);
    cudaGetSymbolAddress((void**)&text2_p,  g_text2_h);
    cudaGetSymbolAddress((void**)&pretxt_p, g_pretxt_h);
    cudaGetSymbolAddress((void**)&pimgb_p,  g_pimgb_h);
    cudaGetSymbolAddress((void**)&rw2h_p,   g_rw2_h);
    cudaGetSymbolAddress((void**)&aw1h_p,   g_aw1_h);
    cudaGetSymbolAddress((void**)&aw2h_p,   g_aw2_h);
    cudaGetSymbolAddress((void**)&rw1h_p,   g_rw1_h);
    cudaGetSymbolAddress((void**)&texth_p,  g_text_h);
    cudaGetSymbolAddress((void**)&imgh_p,   g_img_h);

    dim3 blk128(128);
    dim3 gsmall(16, 8);   // 32x64 tiles over [256 x 1024] -> 128 CTAs

    // prepass: convert all fp32 operands to fp16 (one launch)
    conv_all<<<5632, 256>>>(aw1, aw2, rw1, rw2, text, image,
                            aw1h_p, aw2h_p, rw1h_p, rw2h_p, texth_p, imgh_p);
    // z=0: h16 = relu(text@aw1+ab1); z=1: pimgb = image@rw1[:D]+rb1
    small_pair<<<dim3(16, 8, 2), blk128>>>(
        texth_p, aw1h_p, ab1, h16_p, imgh_p, rw1h_p, rb1, pimgb_p);
    // logits = h @ aw2 + ab2   (fp32 out for softmax)
    small_logits<<<gsmall, blk128>>>(h16_p, aw2h_p, ab2, logits_p);
    // text2 = fp16(text * softmax(logits))
    softmax_mul<<<BSZ, 256>>>(logits_p, text, text2_p);
    // pretxt = fp16(text2 @ rw1[D:])
    small_pretxt<<<gsmall, blk128>>>(text2_p, rw1h_p + (size_t)DD * DD, pretxt_p);
    // big fused GEMM (at register-HMMA floor)
    big_gemm_mma<<<dim3(8, 512), 256>>>(
        pretxt_p, pimgb_p, rw2h_p, image, rb2, out);
}